// round 3
// baseline (speedup 1.0000x reference)
#include <cuda_runtime.h>
#include <cuda_bf16.h>

#define NN     256
#define NT     256
#define NW     8
#define NITER  15
#define SROWS  192          // rows resident in shared memory
#define WS     24           // smem rows per warp
#define WR     8            // register rows per warp (8 warps x 8 = 64 rows)

#define SMEM_BYTES ((SROWS*NN + NW*NN + NN + NN) * 4)

static __device__ __forceinline__ float rcp_nn(float u) {
    // divide_no_nan semantics: 0 where denominator is 0
    return (u == 0.0f) ? 0.0f : __frcp_rn(u);
}

static __device__ __forceinline__ float warp_sum(float t) {
    #pragma unroll
    for (int off = 16; off; off >>= 1)
        t += __shfl_xor_sync(0xFFFFFFFFu, t, off);
    return t;
}

__global__ void __launch_bounds__(NT, 1)
sinkhorn_kernel(const float* __restrict__ g_in, float* __restrict__ g_out)
{
    extern __shared__ float sm[];
    float* xs     = sm;                    // [SROWS][NN]  static copy of x (rows 0..191)
    float* s_part = sm + SROWS * NN;       // [NW][NN]     per-warp column partials
    float* s_rs   = s_part + NW * NN;      // [NN]         1/S_j
    float* s_ra   = s_rs + NN;             // [SROWS]      1/T_i for smem rows

    const int tid  = threadIdx.x;
    const int wid  = tid >> 5;
    const int lane = tid & 31;
    const int cA   = 4 * lane;             // my cols cA..cA+3
    const int cB   = 128 + 4 * lane;       // my cols cB..cB+3
    const int wrow = wid * WS;             // my warp's smem-row block
    const int rrow = SROWS + wid * WR;     // my warp's register-row block (global idx)

    const float* __restrict__ src = g_in  + (size_t)blockIdx.x * NN * NN;
    float*       __restrict__ dst = g_out + (size_t)blockIdx.x * NN * NN;

    // ---- load 192 rows into smem (flat float4 copy, coalesced) ----
    {
        const float4* s4 = (const float4*)src;
        float4* x4 = (float4*)xs;
        #pragma unroll
        for (int i = 0; i < (SROWS * NN / 4) / NT; ++i)
            x4[tid + i * NT] = s4[tid + i * NT];
    }
    // ---- load 64 rows into registers ----
    float4 xrA[WR], xrB[WR];
    #pragma unroll
    for (int k = 0; k < WR; ++k) {
        const float* rp = src + (size_t)(rrow + k) * NN;
        xrA[k] = *(const float4*)(rp + cA);
        xrB[k] = *(const float4*)(rp + cB);
    }

    float ar[WR];                          // 1/T for my register rows
    #pragma unroll
    for (int k = 0; k < WR; ++k) ar[k] = 1.0f;
    if (tid < SROWS) s_ra[tid] = 1.0f;     // A = 1 initially
    __syncthreads();

    float4 rsA = make_float4(0.f,0.f,0.f,0.f);
    float4 rsB = make_float4(0.f,0.f,0.f,0.f);

    for (int it = 0; it < NITER; ++it) {
        // ================= S pass: S_j = sum_i x_ij * A_i =================
        float4 sA = make_float4(0.f,0.f,0.f,0.f);
        float4 sB = make_float4(0.f,0.f,0.f,0.f);
        #pragma unroll 8
        for (int r = 0; r < WS; ++r) {
            const int row = wrow + r;
            const float a = s_ra[row];
            const float4 xa = *(const float4*)&xs[row * NN + cA];
            const float4 xb = *(const float4*)&xs[row * NN + cB];
            sA.x = fmaf(xa.x, a, sA.x); sA.y = fmaf(xa.y, a, sA.y);
            sA.z = fmaf(xa.z, a, sA.z); sA.w = fmaf(xa.w, a, sA.w);
            sB.x = fmaf(xb.x, a, sB.x); sB.y = fmaf(xb.y, a, sB.y);
            sB.z = fmaf(xb.z, a, sB.z); sB.w = fmaf(xb.w, a, sB.w);
        }
        #pragma unroll
        for (int k = 0; k < WR; ++k) {
            const float a = ar[k];
            sA.x = fmaf(xrA[k].x, a, sA.x); sA.y = fmaf(xrA[k].y, a, sA.y);
            sA.z = fmaf(xrA[k].z, a, sA.z); sA.w = fmaf(xrA[k].w, a, sA.w);
            sB.x = fmaf(xrB[k].x, a, sB.x); sB.y = fmaf(xrB[k].y, a, sB.y);
            sB.z = fmaf(xrB[k].z, a, sB.z); sB.w = fmaf(xrB[k].w, a, sB.w);
        }
        *(float4*)&s_part[wid * NN + cA] = sA;
        *(float4*)&s_part[wid * NN + cB] = sB;
        __syncthreads();
        {
            float S = 0.f;
            #pragma unroll
            for (int w = 0; w < NW; ++w) S += s_part[w * NN + tid];
            s_rs[tid] = rcp_nn(S);
        }
        __syncthreads();

        // ================= T pass: T_i = sum_j x_ij * (1/S_j) =================
        rsA = *(const float4*)&s_rs[cA];
        rsB = *(const float4*)&s_rs[cB];
        #pragma unroll 4
        for (int r = 0; r < WS; ++r) {
            const int row = wrow + r;
            const float4 xa = *(const float4*)&xs[row * NN + cA];
            const float4 xb = *(const float4*)&xs[row * NN + cB];
            float t = ((xa.x*rsA.x + xa.y*rsA.y) + (xa.z*rsA.z + xa.w*rsA.w))
                    + ((xb.x*rsB.x + xb.y*rsB.y) + (xb.z*rsB.z + xb.w*rsB.w));
            t = warp_sum(t);
            if (lane == 0) s_ra[row] = rcp_nn(t);   // warp-local: only warp wid reads it
        }
        #pragma unroll
        for (int k = 0; k < WR; ++k) {
            float t = ((xrA[k].x*rsA.x + xrA[k].y*rsA.y) + (xrA[k].z*rsA.z + xrA[k].w*rsA.w))
                    + ((xrB[k].x*rsB.x + xrB[k].y*rsB.y) + (xrB[k].z*rsB.z + xrB[k].w*rsB.w));
            t = warp_sum(t);
            ar[k] = rcp_nn(t);
        }
        __syncwarp();   // order lane-0 s_ra writes before this warp's next S-pass reads
        // no __syncthreads needed: s_ra rows are warp-private, s_part/s_rs are
        // protected by the two barriers at the top of the next iteration.
    }

    // ================= final: y_ij = x_ij * (1/S_j) * (1/T_i) =================
    #pragma unroll 4
    for (int r = 0; r < WS; ++r) {
        const int row = wrow + r;
        const float a = s_ra[row];
        const float4 xa = *(const float4*)&xs[row * NN + cA];
        const float4 xb = *(const float4*)&xs[row * NN + cB];
        float4 ya, yb;
        ya.x = xa.x * rsA.x * a; ya.y = xa.y * rsA.y * a;
        ya.z = xa.z * rsA.z * a; ya.w = xa.w * rsA.w * a;
        yb.x = xb.x * rsB.x * a; yb.y = xb.y * rsB.y * a;
        yb.z = xb.z * rsB.z * a; yb.w = xb.w * rsB.w * a;
        float* wp = dst + (size_t)row * NN;
        *(float4*)(wp + cA) = ya;
        *(float4*)(wp + cB) = yb;
    }
    #pragma unroll
    for (int k = 0; k < WR; ++k) {
        const float a = ar[k];
        float4 ya, yb;
        ya.x = xrA[k].x * rsA.x * a; ya.y = xrA[k].y * rsA.y * a;
        ya.z = xrA[k].z * rsA.z * a; ya.w = xrA[k].w * rsA.w * a;
        yb.x = xrB[k].x * rsB.x * a; yb.y = xrB[k].y * rsB.y * a;
        yb.z = xrB[k].z * rsB.z * a; yb.w = xrB[k].w * rsB.w * a;
        float* wp = dst + (size_t)(rrow + k) * NN;
        *(float4*)(wp + cA) = ya;
        *(float4*)(wp + cB) = yb;
    }
}

extern "C" void kernel_launch(void* const* d_in, const int* in_sizes, int n_in,
                              void* d_out, int out_size) {
    const float* x = (const float*)d_in[0];
    float* y = (float*)d_out;
    const int B = in_sizes[0] / (NN * NN);
    cudaFuncSetAttribute(sinkhorn_kernel,
                         cudaFuncAttributeMaxDynamicSharedMemorySize, SMEM_BYTES);
    sinkhorn_kernel<<<B, NT, SMEM_BYTES>>>(x, y);
}

// round 7
// speedup vs baseline: 1.4599x; 1.4599x over previous
#include <cuda_runtime.h>
#include <cuda_bf16.h>

#define NN     256
#define NT     512
#define NW     16
#define NITER  15
#define SROWS  192          // rows resident in shared memory
#define WS     12           // smem rows per warp  (16*12 = 192)
#define WR     4            // register rows per warp (16*4 = 64)

#define SMEM_FLOATS (SROWS*NN + NW*NN + NN + NN)
#define SMEM_BYTES  (SMEM_FLOATS * 4)

static __device__ __forceinline__ float rcp_nn(float u) {
    // divide_no_nan semantics: 0 where denominator is 0
    return (u == 0.0f) ? 0.0f : __frcp_rn(u);
}

static __device__ __forceinline__ float warp_sum(float t) {
    #pragma unroll
    for (int off = 16; off; off >>= 1)
        t += __shfl_xor_sync(0xFFFFFFFFu, t, off);
    return t;
}

__global__ void __launch_bounds__(NT, 1)
sinkhorn_kernel(const float* __restrict__ g_in, float* __restrict__ g_out)
{
    extern __shared__ float sm[];
    float* xs     = sm;                    // [SROWS][NN]  static copy of x (rows 0..191)
    float* s_part = sm + SROWS * NN;       // [NW][NN]     per-warp column partials
    float* s_rs   = s_part + NW * NN;      // [NN]         1/S_j
    float* s_ra   = s_rs + NN;             // [SROWS]      1/T_i for smem rows

    const int tid  = threadIdx.x;
    const int wid  = tid >> 5;
    const int lane = tid & 31;
    const int cA   = 4 * lane;             // my cols cA..cA+3
    const int cB   = 128 + 4 * lane;       // my cols cB..cB+3
    const int wrow = wid * WS;             // my warp's smem-row block
    const int rrow = SROWS + wid * WR;     // my warp's register-row block (global idx)

    const float* __restrict__ src = g_in  + (size_t)blockIdx.x * NN * NN;
    float*       __restrict__ dst = g_out + (size_t)blockIdx.x * NN * NN;

    // ---- load 192 rows into smem (flat float4 copy, coalesced) ----
    {
        const float4* s4 = (const float4*)src;
        float4* x4 = (float4*)xs;
        #pragma unroll
        for (int i = 0; i < (SROWS * NN / 4) / NT; ++i)
            x4[tid + i * NT] = s4[tid + i * NT];
    }
    // ---- load 64 rows into registers ----
    float4 xrA[WR], xrB[WR];
    #pragma unroll
    for (int k = 0; k < WR; ++k) {
        const float* rp = src + (size_t)(rrow + k) * NN;
        xrA[k] = *(const float4*)(rp + cA);
        xrB[k] = *(const float4*)(rp + cB);
    }

    float ar[WR];                          // 1/T for my register rows
    #pragma unroll
    for (int k = 0; k < WR; ++k) ar[k] = 1.0f;
    if (tid < SROWS) s_ra[tid] = 1.0f;     // A = 1 initially
    __syncthreads();

    float4 rsA = make_float4(0.f,0.f,0.f,0.f);
    float4 rsB = make_float4(0.f,0.f,0.f,0.f);

    for (int it = 0; it < NITER; ++it) {
        // ================= S pass: S_j = sum_i x_ij * A_i =================
        float a[WS];
        #pragma unroll
        for (int r = 0; r < WS; ++r) a[r] = s_ra[wrow + r];   // independent broadcasts

        float4 sA = make_float4(0.f,0.f,0.f,0.f);
        float4 sB = make_float4(0.f,0.f,0.f,0.f);
        #pragma unroll
        for (int r = 0; r < WS; ++r) {
            const int row = wrow + r;
            const float4 xa = *(const float4*)&xs[row * NN + cA];
            const float4 xb = *(const float4*)&xs[row * NN + cB];
            sA.x = fmaf(xa.x, a[r], sA.x); sA.y = fmaf(xa.y, a[r], sA.y);
            sA.z = fmaf(xa.z, a[r], sA.z); sA.w = fmaf(xa.w, a[r], sA.w);
            sB.x = fmaf(xb.x, a[r], sB.x); sB.y = fmaf(xb.y, a[r], sB.y);
            sB.z = fmaf(xb.z, a[r], sB.z); sB.w = fmaf(xb.w, a[r], sB.w);
        }
        #pragma unroll
        for (int k = 0; k < WR; ++k) {
            const float av = ar[k];
            sA.x = fmaf(xrA[k].x, av, sA.x); sA.y = fmaf(xrA[k].y, av, sA.y);
            sA.z = fmaf(xrA[k].z, av, sA.z); sA.w = fmaf(xrA[k].w, av, sA.w);
            sB.x = fmaf(xrB[k].x, av, sB.x); sB.y = fmaf(xrB[k].y, av, sB.y);
            sB.z = fmaf(xrB[k].z, av, sB.z); sB.w = fmaf(xrB[k].w, av, sB.w);
        }
        *(float4*)&s_part[wid * NN + cA] = sA;
        *(float4*)&s_part[wid * NN + cB] = sB;
        __syncthreads();
        if (tid < NN) {
            float S = 0.f;
            #pragma unroll
            for (int w = 0; w < NW; ++w) S += s_part[w * NN + tid];
            s_rs[tid] = rcp_nn(S);
        }
        __syncthreads();

        // ================= T pass: T_i = sum_j x_ij * (1/S_j) =================
        rsA = *(const float4*)&s_rs[cA];
        rsB = *(const float4*)&s_rs[cB];
        #pragma unroll
        for (int r = 0; r < WS; ++r) {
            const int row = wrow + r;
            const float4 xa = *(const float4*)&xs[row * NN + cA];
            const float4 xb = *(const float4*)&xs[row * NN + cB];
            float t = ((xa.x*rsA.x + xa.y*rsA.y) + (xa.z*rsA.z + xa.w*rsA.w))
                    + ((xb.x*rsB.x + xb.y*rsB.y) + (xb.z*rsB.z + xb.w*rsB.w));
            t = warp_sum(t);
            if (lane == 0) s_ra[row] = rcp_nn(t);   // warp-local: only warp wid reads it
        }
        #pragma unroll
        for (int k = 0; k < WR; ++k) {
            float t = ((xrA[k].x*rsA.x + xrA[k].y*rsA.y) + (xrA[k].z*rsA.z + xrA[k].w*rsA.w))
                    + ((xrB[k].x*rsB.x + xrB[k].y*rsB.y) + (xrB[k].z*rsB.z + xrB[k].w*rsB.w));
            t = warp_sum(t);
            ar[k] = rcp_nn(t);
        }
        __syncwarp();   // order lane-0 s_ra writes before this warp's next S-pass reads
        // s_part/s_rs are protected by the two barriers at the top of the next iteration.
    }

    // ================= final: y_ij = x_ij * (1/S_j) * (1/T_i) =================
    #pragma unroll
    for (int r = 0; r < WS; ++r) {
        const int row = wrow + r;
        const float av = s_ra[row];
        const float4 xa = *(const float4*)&xs[row * NN + cA];
        const float4 xb = *(const float4*)&xs[row * NN + cB];
        float4 ya, yb;
        ya.x = xa.x * rsA.x * av; ya.y = xa.y * rsA.y * av;
        ya.z = xa.z * rsA.z * av; ya.w = xa.w * rsA.w * av;
        yb.x = xb.x * rsB.x * av; yb.y = xb.y * rsB.y * av;
        yb.z = xb.z * rsB.z * av; yb.w = xb.w * rsB.w * av;
        float* wp = dst + (size_t)row * NN;
        *(float4*)(wp + cA) = ya;
        *(float4*)(wp + cB) = yb;
    }
    #pragma unroll
    for (int k = 0; k < WR; ++k) {
        const float av = ar[k];
        float4 ya, yb;
        ya.x = xrA[k].x * rsA.x * av; ya.y = xrA[k].y * rsA.y * av;
        ya.z = xrA[k].z * rsA.z * av; ya.w = xrA[k].w * rsA.w * av;
        yb.x = xrB[k].x * rsB.x * av; yb.y = xrB[k].y * rsB.y * av;
        yb.z = xrB[k].z * rsB.z * av; yb.w = xrB[k].w * rsB.w * av;
        float* wp = dst + (size_t)(rrow + k) * NN;
        *(float4*)(wp + cA) = ya;
        *(float4*)(wp + cB) = yb;
    }
}

extern "C" void kernel_launch(void* const* d_in, const int* in_sizes, int n_in,
                              void* d_out, int out_size) {
    const float* x = (const float*)d_in[0];
    float* y = (float*)d_out;
    const int B = in_sizes[0] / (NN * NN);
    cudaFuncSetAttribute(sinkhorn_kernel,
                         cudaFuncAttributeMaxDynamicSharedMemorySize, SMEM_BYTES);
    sinkhorn_kernel<<<B, NT, SMEM_BYTES>>>(x, y);
}

// round 9
// speedup vs baseline: 1.8594x; 1.2737x over previous
#include <cuda_runtime.h>
#include <cuda_bf16.h>

#define NN     256
#define NT     1024
#define NW     32
#define NITER  15
#define SROWS  160          // rows resident in shared memory
#define WS     5            // smem rows per warp   (32*5 = 160)
#define WR     3            // register rows per warp (32*3 = 96)

#define SMEM_FLOATS (SROWS*NN + NW*NN + 4*NN + NN + SROWS)
#define SMEM_BYTES  (SMEM_FLOATS * 4)

typedef unsigned long long u64;

static __device__ __forceinline__ float rcp_nn(float u) {
    return (u == 0.0f) ? 0.0f : __frcp_rn(u);
}
static __device__ __forceinline__ u64 pack2(float lo, float hi) {
    u64 r; asm("mov.b64 %0,{%1,%2};" : "=l"(r) : "f"(lo), "f"(hi)); return r;
}
static __device__ __forceinline__ void fma2(u64& d, u64 a, u64 b) {   // d += a*b (packed f32x2)
    asm("fma.rn.f32x2 %0,%1,%2,%0;" : "+l"(d) : "l"(a), "l"(b));
}
static __device__ __forceinline__ u64 mul2(u64 a, u64 b) {
    u64 r; asm("mul.rn.f32x2 %0,%1,%2;" : "=l"(r) : "l"(a), "l"(b)); return r;
}
static __device__ __forceinline__ float hadd2(u64 v) {
    float lo, hi; asm("mov.b64 {%0,%1},%2;" : "=f"(lo), "=f"(hi) : "l"(v)); return lo + hi;
}
static __device__ __forceinline__ float warp_sum(float t) {
    #pragma unroll
    for (int off = 16; off; off >>= 1)
        t += __shfl_xor_sync(0xFFFFFFFFu, t, off);
    return t;
}

__global__ void __launch_bounds__(NT, 1)
sinkhorn_kernel(const float* __restrict__ g_in, float* __restrict__ g_out)
{
    extern __shared__ float sm[];
    float* xs     = sm;                     // [SROWS][NN] static copy of x
    float* s_part = sm + SROWS * NN;        // [NW][NN]    per-warp column partials
    float* s_q    = s_part + NW * NN;       // [4][NN]     stage-1 partial sums
    float* s_rs   = s_q + 4 * NN;           // [NN]        1/S_j
    float* s_ra   = s_rs + NN;              // [SROWS]     1/T_i for smem rows

    const int tid  = threadIdx.x;
    const int wid  = tid >> 5;
    const int lane = tid & 31;
    const int cA   = 4 * lane;              // my cols cA..cA+3
    const int cB   = 128 + 4 * lane;        // my cols cB..cB+3
    const int wrow = wid * WS;              // my warp's smem-row block
    const int rrow = SROWS + wid * WR;      // my warp's register rows (global idx)

    const float* __restrict__ src = g_in  + (size_t)blockIdx.x * NN * NN;
    float*       __restrict__ dst = g_out + (size_t)blockIdx.x * NN * NN;

    // ---- load 160 rows into smem (flat float4 copy, coalesced) ----
    {
        const float4* s4 = (const float4*)src;
        float4* x4 = (float4*)xs;
        #pragma unroll
        for (int i = 0; i < (SROWS * NN / 4) / NT; ++i)
            x4[tid + i * NT] = s4[tid + i * NT];
    }
    // ---- load 96 rows into registers (packed pairs) ----
    ulonglong2 xrA[WR], xrB[WR];
    #pragma unroll
    for (int k = 0; k < WR; ++k) {
        const float* rp = src + (size_t)(rrow + k) * NN;
        xrA[k] = *(const ulonglong2*)(rp + cA);
        xrB[k] = *(const ulonglong2*)(rp + cB);
    }

    float ar[WR];
    #pragma unroll
    for (int k = 0; k < WR; ++k) ar[k] = 1.0f;
    if (tid < SROWS) s_ra[tid] = 1.0f;
    __syncthreads();

    ulonglong2 rsA, rsB;

    for (int it = 0; it < NITER; ++it) {
        // ============ S pass: S_j = sum_i x_ij * A_i (packed f32x2) ============
        float a[WS];
        #pragma unroll
        for (int r = 0; r < WS; ++r) a[r] = s_ra[wrow + r];

        u64 sA0 = 0, sA1 = 0, sB0 = 0, sB1 = 0;
        #pragma unroll
        for (int r = 0; r < WS; ++r) {
            const int row = wrow + r;
            const ulonglong2 xa = *(const ulonglong2*)&xs[row * NN + cA];
            const ulonglong2 xb = *(const ulonglong2*)&xs[row * NN + cB];
            const u64 aa = pack2(a[r], a[r]);
            fma2(sA0, xa.x, aa); fma2(sA1, xa.y, aa);
            fma2(sB0, xb.x, aa); fma2(sB1, xb.y, aa);
        }
        #pragma unroll
        for (int k = 0; k < WR; ++k) {
            const u64 aa = pack2(ar[k], ar[k]);
            fma2(sA0, xrA[k].x, aa); fma2(sA1, xrA[k].y, aa);
            fma2(sB0, xrB[k].x, aa); fma2(sB1, xrB[k].y, aa);
        }
        *(ulonglong2*)&s_part[wid * NN + cA] = make_ulonglong2(sA0, sA1);
        *(ulonglong2*)&s_part[wid * NN + cB] = make_ulonglong2(sB0, sB1);
        __syncthreads();

        // stage 1: 1024 threads, each sums 8 of the 32 partials for one column
        {
            const int col = tid & (NN - 1);
            const int q   = tid >> 8;              // 0..3
            float s = 0.f;
            #pragma unroll
            for (int w = 0; w < 8; ++w) s += s_part[(q * 8 + w) * NN + col];
            s_q[q * NN + col] = s;
        }
        __syncthreads();
        // stage 2: 256 threads finish and invert
        if (tid < NN) {
            float S = s_q[tid] + s_q[NN + tid] + s_q[2 * NN + tid] + s_q[3 * NN + tid];
            s_rs[tid] = rcp_nn(S);
        }
        __syncthreads();

        // ============ T pass: T_i = sum_j x_ij * (1/S_j) ============
        rsA = *(const ulonglong2*)&s_rs[cA];
        rsB = *(const ulonglong2*)&s_rs[cB];
        #pragma unroll
        for (int r = 0; r < WS; ++r) {
            const int row = wrow + r;
            const ulonglong2 xa = *(const ulonglong2*)&xs[row * NN + cA];
            const ulonglong2 xb = *(const ulonglong2*)&xs[row * NN + cB];
            u64 tp = 0;
            fma2(tp, xa.x, rsA.x); fma2(tp, xa.y, rsA.y);
            fma2(tp, xb.x, rsB.x); fma2(tp, xb.y, rsB.y);
            float t = warp_sum(hadd2(tp));
            if (lane == 0) s_ra[row] = rcp_nn(t);   // warp-private row
        }
        #pragma unroll
        for (int k = 0; k < WR; ++k) {
            u64 tp = 0;
            fma2(tp, xrA[k].x, rsA.x); fma2(tp, xrA[k].y, rsA.y);
            fma2(tp, xrB[k].x, rsB.x); fma2(tp, xrB[k].y, rsB.y);
            ar[k] = rcp_nn(warp_sum(hadd2(tp)));
        }
        __syncwarp();   // order lane-0 s_ra writes before this warp's next S-pass reads
    }

    // ============ final: y_ij = x_ij * (1/S_j) * (1/T_i) ============
    #pragma unroll
    for (int r = 0; r < WS; ++r) {
        const int row = wrow + r;
        const float av = s_ra[row];
        const u64 aa = pack2(av, av);
        const ulonglong2 xa = *(const ulonglong2*)&xs[row * NN + cA];
        const ulonglong2 xb = *(const ulonglong2*)&xs[row * NN + cB];
        ulonglong2 ya, yb;
        ya.x = mul2(mul2(xa.x, rsA.x), aa); ya.y = mul2(mul2(xa.y, rsA.y), aa);
        yb.x = mul2(mul2(xb.x, rsB.x), aa); yb.y = mul2(mul2(xb.y, rsB.y), aa);
        float* wp = dst + (size_t)row * NN;
        *(ulonglong2*)(wp + cA) = ya;
        *(ulonglong2*)(wp + cB) = yb;
    }
    #pragma unroll
    for (int k = 0; k < WR; ++k) {
        const u64 aa = pack2(ar[k], ar[k]);
        ulonglong2 ya, yb;
        ya.x = mul2(mul2(xrA[k].x, rsA.x), aa); ya.y = mul2(mul2(xrA[k].y, rsA.y), aa);
        yb.x = mul2(mul2(xrB[k].x, rsB.x), aa); yb.y = mul2(mul2(xrB[k].y, rsB.y), aa);
        float* wp = dst + (size_t)(rrow + k) * NN;
        *(ulonglong2*)(wp + cA) = ya;
        *(ulonglong2*)(wp + cB) = yb;
    }
}

extern "C" void kernel_launch(void* const* d_in, const int* in_sizes, int n_in,
                              void* d_out, int out_size) {
    const float* x = (const float*)d_in[0];
    float* y = (float*)d_out;
    const int B = in_sizes[0] / (NN * NN);
    cudaFuncSetAttribute(sinkhorn_kernel,
                         cudaFuncAttributeMaxDynamicSharedMemorySize, SMEM_BYTES);
    sinkhorn_kernel<<<B, NT, SMEM_BYTES>>>(x, y);
}

// round 10
// speedup vs baseline: 2.1555x; 1.1592x over previous
#include <cuda_runtime.h>
#include <cuda_bf16.h>

#define NN     256
#define NT     1024
#define NW     32
#define NITER  15
#define SROWS  160          // rows resident in shared memory
#define WS     5            // smem rows per warp   (32*5 = 160)
#define WR     3            // register rows per warp (32*3 = 96)

#define SMEM_FLOATS (SROWS*NN + NW*NN + 4*NN + NN)
#define SMEM_BYTES  (SMEM_FLOATS * 4)

typedef unsigned long long u64;

static __device__ __forceinline__ float rcp_nn(float u) {
    return (u == 0.0f) ? 0.0f : __frcp_rn(u);
}
static __device__ __forceinline__ u64 pack2(float lo, float hi) {
    u64 r; asm("mov.b64 %0,{%1,%2};" : "=l"(r) : "f"(lo), "f"(hi)); return r;
}
static __device__ __forceinline__ void fma2(u64& d, u64 a, u64 b) {   // d += a*b
    asm("fma.rn.f32x2 %0,%1,%2,%0;" : "+l"(d) : "l"(a), "l"(b));
}
static __device__ __forceinline__ u64 mul2(u64 a, u64 b) {
    u64 r; asm("mul.rn.f32x2 %0,%1,%2;" : "=l"(r) : "l"(a), "l"(b)); return r;
}
static __device__ __forceinline__ u64 add2(u64 a, u64 b) {
    u64 r; asm("add.rn.f32x2 %0,%1,%2;" : "=l"(r) : "l"(a), "l"(b)); return r;
}
static __device__ __forceinline__ float hadd2(u64 v) {
    float lo, hi; asm("mov.b64 {%0,%1},%2;" : "=f"(lo), "=f"(hi) : "l"(v)); return lo + hi;
}
static __device__ __forceinline__ float warp_sum(float t) {
    #pragma unroll
    for (int off = 16; off; off >>= 1)
        t += __shfl_xor_sync(0xFFFFFFFFu, t, off);
    return t;
}

__global__ void __launch_bounds__(NT, 1)
sinkhorn_kernel(const float* __restrict__ g_in, float* __restrict__ g_out)
{
    extern __shared__ float sm[];
    float* xs     = sm;                     // [SROWS][NN] static copy of x
    float* s_part = sm + SROWS * NN;        // [NW][NN]    per-warp column partials
    float* s_q    = s_part + NW * NN;       // [4][NN]     stage-1 partial sums
    float* s_rs   = s_q + 4 * NN;           // [NN]        1/S_j

    const int tid  = threadIdx.x;
    const int wid  = tid >> 5;
    const int lane = tid & 31;
    const int cA   = 4 * lane;              // my cols cA..cA+3
    const int cB   = 128 + 4 * lane;        // my cols cB..cB+3
    const int wrow = wid * WS;              // my warp's smem-row block
    const int rrow = SROWS + wid * WR;      // my warp's register rows (global idx)

    const float* __restrict__ src = g_in  + (size_t)blockIdx.x * NN * NN;
    float*       __restrict__ dst = g_out + (size_t)blockIdx.x * NN * NN;

    // ---- load 160 rows into smem (flat float4 copy, coalesced) ----
    {
        const float4* s4 = (const float4*)src;
        float4* x4 = (float4*)xs;
        #pragma unroll
        for (int i = 0; i < (SROWS * NN / 4) / NT; ++i)
            x4[tid + i * NT] = s4[tid + i * NT];
    }
    // ---- load 96 rows into registers (packed pairs) ----
    ulonglong2 xrA[WR], xrB[WR];
    #pragma unroll
    for (int k = 0; k < WR; ++k) {
        const float* rp = src + (size_t)(rrow + k) * NN;
        xrA[k] = *(const ulonglong2*)(rp + cA);
        xrB[k] = *(const ulonglong2*)(rp + cB);
    }
    __syncthreads();

    // ================= prepass: S_j = colsum(x) -> s_rs = 1/S ==============
    {
        u64 sA0 = 0, sA1 = 0, sB0 = 0, sB1 = 0;
        #pragma unroll
        for (int r = 0; r < WS; ++r) {
            const int row = wrow + r;
            const ulonglong2 xa = *(const ulonglong2*)&xs[row * NN + cA];
            const ulonglong2 xb = *(const ulonglong2*)&xs[row * NN + cB];
            sA0 = add2(sA0, xa.x); sA1 = add2(sA1, xa.y);
            sB0 = add2(sB0, xb.x); sB1 = add2(sB1, xb.y);
        }
        #pragma unroll
        for (int k = 0; k < WR; ++k) {
            sA0 = add2(sA0, xrA[k].x); sA1 = add2(sA1, xrA[k].y);
            sB0 = add2(sB0, xrB[k].x); sB1 = add2(sB1, xrB[k].y);
        }
        *(ulonglong2*)&s_part[wid * NN + cA] = make_ulonglong2(sA0, sA1);
        *(ulonglong2*)&s_part[wid * NN + cB] = make_ulonglong2(sB0, sB1);
        __syncthreads();
        {
            const int col = tid & (NN - 1);
            const int q   = tid >> 8;
            float s = 0.f;
            #pragma unroll
            for (int w = 0; w < 8; ++w) s += s_part[(q * 8 + w) * NN + col];
            s_q[q * NN + col] = s;
        }
        __syncthreads();
        if (tid < NN) {
            float S = s_q[tid] + s_q[NN + tid] + s_q[2 * NN + tid] + s_q[3 * NN + tid];
            s_rs[tid] = rcp_nn(S);
        }
        __syncthreads();
    }

    // ====== fused passes: per row, T_i with current rs; accumulate next S ======
    for (int it = 0; it < NITER - 1; ++it) {
        const ulonglong2 rsA = *(const ulonglong2*)&s_rs[cA];
        const ulonglong2 rsB = *(const ulonglong2*)&s_rs[cB];
        u64 sA0 = 0, sA1 = 0, sB0 = 0, sB1 = 0;
        #pragma unroll
        for (int r = 0; r < WS; ++r) {
            const int row = wrow + r;
            const ulonglong2 xa = *(const ulonglong2*)&xs[row * NN + cA];
            const ulonglong2 xb = *(const ulonglong2*)&xs[row * NN + cB];
            u64 ta = mul2(xa.x, rsA.x); fma2(ta, xa.y, rsA.y);
            u64 tb = mul2(xb.x, rsB.x); fma2(tb, xb.y, rsB.y);
            const float t = warp_sum(hadd2(add2(ta, tb)));
            const float a = rcp_nn(t);
            const u64 aa = pack2(a, a);
            fma2(sA0, xa.x, aa); fma2(sA1, xa.y, aa);
            fma2(sB0, xb.x, aa); fma2(sB1, xb.y, aa);
        }
        #pragma unroll
        for (int k = 0; k < WR; ++k) {
            u64 ta = mul2(xrA[k].x, rsA.x); fma2(ta, xrA[k].y, rsA.y);
            u64 tb = mul2(xrB[k].x, rsB.x); fma2(tb, xrB[k].y, rsB.y);
            const float t = warp_sum(hadd2(add2(ta, tb)));
            const float a = rcp_nn(t);
            const u64 aa = pack2(a, a);
            fma2(sA0, xrA[k].x, aa); fma2(sA1, xrA[k].y, aa);
            fma2(sB0, xrB[k].x, aa); fma2(sB1, xrB[k].y, aa);
        }
        *(ulonglong2*)&s_part[wid * NN + cA] = make_ulonglong2(sA0, sA1);
        *(ulonglong2*)&s_part[wid * NN + cB] = make_ulonglong2(sB0, sB1);
        __syncthreads();
        {
            const int col = tid & (NN - 1);
            const int q   = tid >> 8;
            float s = 0.f;
            #pragma unroll
            for (int w = 0; w < 8; ++w) s += s_part[(q * 8 + w) * NN + col];
            s_q[q * NN + col] = s;
        }
        __syncthreads();
        if (tid < NN) {
            float S = s_q[tid] + s_q[NN + tid] + s_q[2 * NN + tid] + s_q[3 * NN + tid];
            s_rs[tid] = rcp_nn(S);
        }
        __syncthreads();
    }

    // ====== final pass (iteration 15): compute a_i and write y = x*rs*a ======
    {
        const ulonglong2 rsA = *(const ulonglong2*)&s_rs[cA];
        const ulonglong2 rsB = *(const ulonglong2*)&s_rs[cB];
        #pragma unroll
        for (int r = 0; r < WS; ++r) {
            const int row = wrow + r;
            const ulonglong2 xa = *(const ulonglong2*)&xs[row * NN + cA];
            const ulonglong2 xb = *(const ulonglong2*)&xs[row * NN + cB];
            u64 ta = mul2(xa.x, rsA.x); fma2(ta, xa.y, rsA.y);
            u64 tb = mul2(xb.x, rsB.x); fma2(tb, xb.y, rsB.y);
            const float t = warp_sum(hadd2(add2(ta, tb)));
            const float a = rcp_nn(t);
            const u64 aa = pack2(a, a);
            ulonglong2 ya, yb;
            ya.x = mul2(mul2(xa.x, rsA.x), aa); ya.y = mul2(mul2(xa.y, rsA.y), aa);
            yb.x = mul2(mul2(xb.x, rsB.x), aa); yb.y = mul2(mul2(xb.y, rsB.y), aa);
            float* wp = dst + (size_t)row * NN;
            *(ulonglong2*)(wp + cA) = ya;
            *(ulonglong2*)(wp + cB) = yb;
        }
        #pragma unroll
        for (int k = 0; k < WR; ++k) {
            u64 ta = mul2(xrA[k].x, rsA.x); fma2(ta, xrA[k].y, rsA.y);
            u64 tb = mul2(xrB[k].x, rsB.x); fma2(tb, xrB[k].y, rsB.y);
            const float t = warp_sum(hadd2(add2(ta, tb)));
            const float a = rcp_nn(t);
            const u64 aa = pack2(a, a);
            ulonglong2 ya, yb;
            ya.x = mul2(mul2(xrA[k].x, rsA.x), aa); ya.y = mul2(mul2(xrA[k].y, rsA.y), aa);
            yb.x = mul2(mul2(xrB[k].x, rsB.x), aa); yb.y = mul2(mul2(xrB[k].y, rsB.y), aa);
            float* wp = dst + (size_t)(rrow + k) * NN;
            *(ulonglong2*)(wp + cA) = ya;
            *(ulonglong2*)(wp + cB) = yb;
        }
    }
}

extern "C" void kernel_launch(void* const* d_in, const int* in_sizes, int n_in,
                              void* d_out, int out_size) {
    const float* x = (const float*)d_in[0];
    float* y = (float*)d_out;
    const int B = in_sizes[0] / (NN * NN);
    cudaFuncSetAttribute(sinkhorn_kernel,
                         cudaFuncAttributeMaxDynamicSharedMemorySize, SMEM_BYTES);
    sinkhorn_kernel<<<B, NT, SMEM_BYTES>>>(x, y);
}